// round 5
// baseline (speedup 1.0000x reference)
#include <cuda_runtime.h>
#include <cuda_bf16.h>

#define B 1024
#define L 1024
#define NCAT 20
#define NNUM 10
#define E 32
#define A 128
#define H 256
#define TOPK 30

// scratch (no cudaMalloc allowed)
__device__ float g_fused[B * 4 * E];   // [B,128]
__device__ float g_h0[B * H];
__device__ float g_h1[B * H];

// ---------------------------------------------------------------------------
// K1: one block per batch row. Attention (score -> top30 -> softmax -> pool)
//     + all small projections -> fused[b, 0:128]
// ---------------------------------------------------------------------------
__global__ __launch_bounds__(256) void k_attn(
    const int* __restrict__ cats, const float* __restrict__ nums,
    const int* __restrict__ seqs, const int* __restrict__ tgt_ids,
    const float* __restrict__ cat_emb, const float* __restrict__ seq_emb,
    const float* __restrict__ Wnum, const float* __restrict__ bnum,
    const float* __restrict__ Wq, const float* __restrict__ Wk,
    const float* __restrict__ Wv, const float* __restrict__ Wo,
    const float* __restrict__ bo, const float* __restrict__ Wpool,
    const float* __restrict__ bpool)
{
    const int b = blockIdx.x;
    const int tid = threadIdx.x;
    const int lane = tid & 31;
    const int warp = tid >> 5;

    __shared__ float s_scores[L];
    __shared__ float s_tgt[E];
    __shared__ float s_q[A];
    __shared__ float s_qk[E];
    __shared__ float s_cat[NCAT * E];      // 640
    __shared__ float s_cpart[8][E];
    __shared__ float s_red[8];
    __shared__ int   s_redi[8];
    __shared__ float s_topv[TOPK];
    __shared__ int   s_topi[TOPK];
    __shared__ float s_w[TOPK];
    __shared__ float s_pool[E];
    __shared__ float s_vsum[A];

    const int tgt = tgt_ids[b];
    if (tid < E) s_tgt[tid] = cat_emb[(size_t)tgt * E + tid];
    for (int i = tid; i < NCAT * E; i += 256) {
        int j = i >> 5, e = i & 31;
        s_cat[i] = cat_emb[(size_t)cats[b * NCAT + j] * E + e];
    }
    __syncthreads();

    // q = tgt_e @ Wq  [A]
    if (tid < A) {
        float acc = 0.f;
        #pragma unroll
        for (int e = 0; e < E; e++) acc += s_tgt[e] * Wq[e * A + tid];
        s_q[tid] = acc;
    }
    __syncthreads();

    // qk[e] = (Wk @ q)[e] / sqrt(A)   — 8 warps, 4 e's each
    {
        #pragma unroll
        for (int i = 0; i < 4; i++) {
            int e = warp * 4 + i;
            float acc = Wk[e * A + lane]      * s_q[lane]
                      + Wk[e * A + lane + 32] * s_q[lane + 32]
                      + Wk[e * A + lane + 64] * s_q[lane + 64]
                      + Wk[e * A + lane + 96] * s_q[lane + 96];
            #pragma unroll
            for (int o = 16; o; o >>= 1) acc += __shfl_xor_sync(~0u, acc, o);
            if (lane == 0) s_qk[e] = acc * 0.08838834764831845f; // 1/sqrt(128)
        }
    }
    __syncthreads();

    // scores[l] = seq_emb[seqs[b,l]] . qk
    for (int l = tid; l < L; l += 256) {
        const float4* row = (const float4*)(seq_emb + (size_t)seqs[b * L + l] * E);
        float acc = 0.f;
        #pragma unroll
        for (int c = 0; c < 8; c++) {
            float4 r = row[c];
            acc += r.x * s_qk[4 * c] + r.y * s_qk[4 * c + 1]
                 + r.z * s_qk[4 * c + 2] + r.w * s_qk[4 * c + 3];
        }
        s_scores[l] = acc;
    }
    __syncthreads();

    // top-30 by iterative argmax (first-occurrence tiebreak, matches lax.top_k)
    for (int it = 0; it < TOPK; it++) {
        float best = -1e30f; int bi = 0x7fffffff;
        for (int l = tid; l < L; l += 256) {
            float v = s_scores[l];
            if (v > best) { best = v; bi = l; }
        }
        #pragma unroll
        for (int o = 16; o; o >>= 1) {
            float ov = __shfl_xor_sync(~0u, best, o);
            int   oi = __shfl_xor_sync(~0u, bi, o);
            if (ov > best || (ov == best && oi < bi)) { best = ov; bi = oi; }
        }
        if (lane == 0) { s_red[warp] = best; s_redi[warp] = bi; }
        __syncthreads();
        if (tid == 0) {
            float bb = s_red[0]; int bbi = s_redi[0];
            #pragma unroll
            for (int w = 1; w < 8; w++)
                if (s_red[w] > bb || (s_red[w] == bb && s_redi[w] < bbi)) {
                    bb = s_red[w]; bbi = s_redi[w];
                }
            s_topv[it] = bb; s_topi[it] = bbi;
            s_scores[bbi] = -1e30f;
        }
        __syncthreads();
    }

    // softmax over the 30 values (warp 0)
    if (tid < 32) {
        float v = (tid < TOPK) ? s_topv[tid] : -1e30f;
        float m = v;
        #pragma unroll
        for (int o = 16; o; o >>= 1) m = fmaxf(m, __shfl_xor_sync(~0u, m, o));
        float ex = (tid < TOPK) ? __expf(v - m) : 0.f;
        float s = ex;
        #pragma unroll
        for (int o = 16; o; o >>= 1) s += __shfl_xor_sync(~0u, s, o);
        if (tid < TOPK) s_w[tid] = ex / s;
    }
    __syncthreads();

    // pooled embedding: sum_k w[k] * seq_emb[idx_k]   [E]
    if (tid < E) {
        float acc = 0.f;
        #pragma unroll 5
        for (int k = 0; k < TOPK; k++)
            acc += s_w[k] * seq_emb[(size_t)seqs[b * L + s_topi[k]] * E + tid];
        s_pool[tid] = acc;
    }
    // cat_pool partials (all 256 threads): chunk of 80 flat-indices each
    {
        int e = tid & 31, chunk = tid >> 5;
        float acc = 0.f;
        int i0 = chunk * 80;
        #pragma unroll 8
        for (int i = i0; i < i0 + 80; i++) acc += s_cat[i] * Wpool[i * E + e];
        s_cpart[chunk][e] = acc;
    }
    __syncthreads();

    // vsum = pooled @ Wv  [A]
    if (tid < A) {
        float acc = 0.f;
        #pragma unroll
        for (int e = 0; e < E; e++) acc += s_pool[e] * Wv[e * A + tid];
        s_vsum[tid] = acc;
    }
    __syncthreads();

    if (tid < E) {
        // interest = vsum @ Wo + bo
        float inter = bo[tid];
        #pragma unroll 8
        for (int a = 0; a < A; a++) inter += s_vsum[a] * Wo[a * E + tid];
        // cat_pool
        float cp = bpool[tid];
        #pragma unroll
        for (int c = 0; c < 8; c++) cp += s_cpart[c][tid];
        // num_e
        float ne = bnum[tid];
        #pragma unroll
        for (int j = 0; j < NNUM; j++) ne += nums[b * NNUM + j] * Wnum[j * E + tid];

        float* f = g_fused + (size_t)b * 128;
        f[tid]      = s_tgt[tid];
        f[32 + tid] = inter;
        f[64 + tid] = cp;
        f[96 + tid] = ne;
    }
}

// ---------------------------------------------------------------------------
// K2: h0 = relu(fused @ Wmlp + bmlp)   [B,256]; 16 rows/block, 64 blocks
// ---------------------------------------------------------------------------
__global__ __launch_bounds__(256) void k_mlp1(const float* __restrict__ Wmlp,
                                              const float* __restrict__ bmlp)
{
    const int r0 = blockIdx.x * 16;
    const int c = threadIdx.x;
    __shared__ float xs[16][128];
    for (int i = c; i < 16 * 128; i += 256) xs[i >> 7][i & 127] = g_fused[r0 * 128 + i];
    __syncthreads();

    float acc[16];
    const float bc = bmlp[c];
    #pragma unroll
    for (int r = 0; r < 16; r++) acc[r] = bc;
    for (int k = 0; k < 128; k++) {
        float w = Wmlp[k * H + c];
        #pragma unroll
        for (int r = 0; r < 16; r++) acc[r] += xs[r][k] * w;
    }
    #pragma unroll
    for (int r = 0; r < 16; r++) g_h0[(size_t)(r0 + r) * H + c] = fmaxf(acc[r], 0.f);
}

// ---------------------------------------------------------------------------
// K3: QNN block  Y = X + ((X@W1+b1)*(X@W2+b2))@Wp + bp
//     8 rows/block, 256 col-threads, 128 blocks.
//     mode: 0 = g_h0 -> g_h1 ; 1 = g_h1 -> final out (fused Wout dot)
// ---------------------------------------------------------------------------
__global__ __launch_bounds__(256) void k_qnn(
    const float* __restrict__ W1, const float* __restrict__ b1,
    const float* __restrict__ W2, const float* __restrict__ b2,
    const float* __restrict__ Wp, const float* __restrict__ bp,
    const float* __restrict__ Wout, const float* __restrict__ bout,
    float* __restrict__ out, int mode)
{
    constexpr int MT = 8;
    const int r0 = blockIdx.x * MT;
    const int c = threadIdx.x;
    const float* X = (mode == 0) ? g_h0 : g_h1;

    __shared__ float xs[MT][H];
    __shared__ float qs[MT][H];
    for (int i = c; i < MT * H; i += 256) xs[i >> 8][i & 255] = X[(size_t)r0 * H + i];
    __syncthreads();

    float a1[MT], a2[MT];
    const float b1c = b1[c], b2c = b2[c];
    #pragma unroll
    for (int r = 0; r < MT; r++) { a1[r] = b1c; a2[r] = b2c; }
    for (int k = 0; k < H; k++) {
        float w1 = W1[k * H + c];
        float w2 = W2[k * H + c];
        #pragma unroll
        for (int r = 0; r < MT; r++) {
            float x = xs[r][k];
            a1[r] += x * w1;
            a2[r] += x * w2;
        }
    }
    #pragma unroll
    for (int r = 0; r < MT; r++) qs[r][c] = a1[r] * a2[r];
    __syncthreads();

    float ay[MT];
    const float bpc = bp[c];
    #pragma unroll
    for (int r = 0; r < MT; r++) ay[r] = bpc;
    for (int k = 0; k < H; k++) {
        float wp = Wp[k * H + c];
        #pragma unroll
        for (int r = 0; r < MT; r++) ay[r] += qs[r][k] * wp;
    }
    #pragma unroll
    for (int r = 0; r < MT; r++) ay[r] += xs[r][c];

    if (mode == 0) {
        #pragma unroll
        for (int r = 0; r < MT; r++) g_h1[(size_t)(r0 + r) * H + c] = ay[r];
    } else {
        // final: out[row] = ay_row . Wout + bout
        const float wo = Wout[c];
        __shared__ float red[8];
        for (int r = 0; r < MT; r++) {
            float p = ay[r] * wo;
            #pragma unroll
            for (int o = 16; o; o >>= 1) p += __shfl_xor_sync(~0u, p, o);
            if ((c & 31) == 0) red[c >> 5] = p;
            __syncthreads();
            if (c == 0) {
                float s = 0.f;
                #pragma unroll
                for (int w = 0; w < 8; w++) s += red[w];
                out[r0 + r] = s + bout[0];
            }
            __syncthreads();
        }
    }
}

// ---------------------------------------------------------------------------
extern "C" void kernel_launch(void* const* d_in, const int* in_sizes, int n_in,
                              void* d_out, int out_size)
{
    const int*   cats    = (const int*)  d_in[0];
    const float* nums    = (const float*)d_in[1];
    const int*   seqs    = (const int*)  d_in[2];
    const int*   tgt_ids = (const int*)  d_in[3];
    const float* cat_emb = (const float*)d_in[4];
    const float* seq_emb = (const float*)d_in[5];
    const float* Wnum    = (const float*)d_in[6];
    const float* bnum    = (const float*)d_in[7];
    const float* Wq      = (const float*)d_in[8];
    const float* Wk      = (const float*)d_in[9];
    const float* Wv      = (const float*)d_in[10];
    const float* Wo      = (const float*)d_in[11];
    const float* bo      = (const float*)d_in[12];
    const float* Wpool   = (const float*)d_in[13];
    const float* bpool   = (const float*)d_in[14];
    const float* Wmlp    = (const float*)d_in[15];
    const float* bmlp    = (const float*)d_in[16];
    const float* q1_W1   = (const float*)d_in[17];
    const float* q1_b1   = (const float*)d_in[18];
    const float* q1_W2   = (const float*)d_in[19];
    const float* q1_b2   = (const float*)d_in[20];
    const float* q1_Wp   = (const float*)d_in[21];
    const float* q1_bp   = (const float*)d_in[22];
    const float* q2_W1   = (const float*)d_in[23];
    const float* q2_b1   = (const float*)d_in[24];
    const float* q2_W2   = (const float*)d_in[25];
    const float* q2_b2   = (const float*)d_in[26];
    const float* q2_Wp   = (const float*)d_in[27];
    const float* q2_bp   = (const float*)d_in[28];
    const float* Wout    = (const float*)d_in[29];
    const float* bout    = (const float*)d_in[30];
    float* out = (float*)d_out;

    k_attn<<<B, 256>>>(cats, nums, seqs, tgt_ids, cat_emb, seq_emb,
                       Wnum, bnum, Wq, Wk, Wv, Wo, bo, Wpool, bpool);
    k_mlp1<<<B / 16, 256>>>(Wmlp, bmlp);
    k_qnn<<<B / 8, 256>>>(q1_W1, q1_b1, q1_W2, q1_b2, q1_Wp, q1_bp,
                          Wout, bout, out, 0);
    k_qnn<<<B / 8, 256>>>(q2_W1, q2_b1, q2_W2, q2_b2, q2_Wp, q2_bp,
                          Wout, bout, out, 1);
}

// round 7
// speedup vs baseline: 1.3593x; 1.3593x over previous
#include <cuda_runtime.h>
#include <cuda_bf16.h>

#define B 1024
#define L 1024
#define NCAT 20
#define NNUM 10
#define E 32
#define A 128
#define H 256
#define TOPK 30

// scratch (no cudaMalloc allowed)
__device__ float g_fused[B * 4 * E];   // [B,128]
__device__ float g_h0[B * H];
__device__ float g_h1[B * H];

// ---------------------------------------------------------------------------
// cp.async helpers
// ---------------------------------------------------------------------------
__device__ __forceinline__ void cp16(void* dst, const void* src) {
    unsigned d = (unsigned)__cvta_generic_to_shared(dst);
    asm volatile("cp.async.cg.shared.global [%0], [%1], 16;" :: "r"(d), "l"(src));
}
__device__ __forceinline__ void cp_commit() {
    asm volatile("cp.async.commit_group;");
}
__device__ __forceinline__ void cp_wait1() {
    asm volatile("cp.async.wait_group 1;");
}
__device__ __forceinline__ void cp_wait0() {
    asm volatile("cp.async.wait_group 0;");
}

// ---------------------------------------------------------------------------
// K1: one block per batch row. Attention (score -> top30 -> softmax -> pool)
//     + all small projections -> fused[b, 0:128]
// ---------------------------------------------------------------------------
__global__ __launch_bounds__(256) void k_attn(
    const int* __restrict__ cats, const float* __restrict__ nums,
    const int* __restrict__ seqs, const int* __restrict__ tgt_ids,
    const float* __restrict__ cat_emb, const float* __restrict__ seq_emb,
    const float* __restrict__ Wnum, const float* __restrict__ bnum,
    const float* __restrict__ Wq, const float* __restrict__ Wk,
    const float* __restrict__ Wv, const float* __restrict__ Wo,
    const float* __restrict__ bo, const float* __restrict__ Wpool,
    const float* __restrict__ bpool)
{
    const int b = blockIdx.x;
    const int tid = threadIdx.x;
    const int lane = tid & 31;
    const int warp = tid >> 5;

    __shared__ float s_scores[L];
    __shared__ float s_tgt[E];
    __shared__ float s_q[A];
    __shared__ float s_qk[E];
    __shared__ float s_cat[NCAT * E];
    __shared__ float s_cpart[8][E];
    __shared__ float s_red[8];
    __shared__ int   s_redi[8];
    __shared__ float s_topv[TOPK];
    __shared__ int   s_topi[TOPK];
    __shared__ float s_w[TOPK];
    __shared__ float s_pool[E];
    __shared__ float s_vsum[A];

    const int tgt = tgt_ids[b];
    if (tid < E) s_tgt[tid] = cat_emb[(size_t)tgt * E + tid];
    for (int i = tid; i < NCAT * E; i += 256) {
        int j = i >> 5, e = i & 31;
        s_cat[i] = cat_emb[(size_t)cats[b * NCAT + j] * E + e];
    }
    __syncthreads();

    // q = tgt_e @ Wq  [A]
    if (tid < A) {
        float acc = 0.f;
        #pragma unroll
        for (int e = 0; e < E; e++) acc += s_tgt[e] * Wq[e * A + tid];
        s_q[tid] = acc;
    }
    __syncthreads();

    // qk[e] = (Wk @ q)[e] / sqrt(A)
    {
        #pragma unroll
        for (int i = 0; i < 4; i++) {
            int e = warp * 4 + i;
            float acc = Wk[e * A + lane]      * s_q[lane]
                      + Wk[e * A + lane + 32] * s_q[lane + 32]
                      + Wk[e * A + lane + 64] * s_q[lane + 64]
                      + Wk[e * A + lane + 96] * s_q[lane + 96];
            #pragma unroll
            for (int o = 16; o; o >>= 1) acc += __shfl_xor_sync(~0u, acc, o);
            if (lane == 0) s_qk[e] = acc * 0.08838834764831845f;
        }
    }
    __syncthreads();

    // scores[l] = seq_emb[seqs[b,l]] . qk
    for (int l = tid; l < L; l += 256) {
        const float4* row = (const float4*)(seq_emb + (size_t)seqs[b * L + l] * E);
        float acc = 0.f;
        #pragma unroll
        for (int c = 0; c < 8; c++) {
            float4 r = row[c];
            acc += r.x * s_qk[4 * c] + r.y * s_qk[4 * c + 1]
                 + r.z * s_qk[4 * c + 2] + r.w * s_qk[4 * c + 3];
        }
        s_scores[l] = acc;
    }
    __syncthreads();

    // top-30 by iterative argmax
    for (int it = 0; it < TOPK; it++) {
        float best = -1e30f; int bi = 0x7fffffff;
        for (int l = tid; l < L; l += 256) {
            float v = s_scores[l];
            if (v > best) { best = v; bi = l; }
        }
        #pragma unroll
        for (int o = 16; o; o >>= 1) {
            float ov = __shfl_xor_sync(~0u, best, o);
            int   oi = __shfl_xor_sync(~0u, bi, o);
            if (ov > best || (ov == best && oi < bi)) { best = ov; bi = oi; }
        }
        if (lane == 0) { s_red[warp] = best; s_redi[warp] = bi; }
        __syncthreads();
        if (tid == 0) {
            float bb = s_red[0]; int bbi = s_redi[0];
            #pragma unroll
            for (int w = 1; w < 8; w++)
                if (s_red[w] > bb || (s_red[w] == bb && s_redi[w] < bbi)) {
                    bb = s_red[w]; bbi = s_redi[w];
                }
            s_topv[it] = bb; s_topi[it] = bbi;
            s_scores[bbi] = -1e30f;
        }
        __syncthreads();
    }

    // softmax over the 30 values
    if (tid < 32) {
        float v = (tid < TOPK) ? s_topv[tid] : -1e30f;
        float m = v;
        #pragma unroll
        for (int o = 16; o; o >>= 1) m = fmaxf(m, __shfl_xor_sync(~0u, m, o));
        float ex = (tid < TOPK) ? __expf(v - m) : 0.f;
        float s = ex;
        #pragma unroll
        for (int o = 16; o; o >>= 1) s += __shfl_xor_sync(~0u, s, o);
        if (tid < TOPK) s_w[tid] = ex / s;
    }
    __syncthreads();

    if (tid < E) {
        float acc = 0.f;
        #pragma unroll 5
        for (int k = 0; k < TOPK; k++)
            acc += s_w[k] * seq_emb[(size_t)seqs[b * L + s_topi[k]] * E + tid];
        s_pool[tid] = acc;
    }
    {
        int e = tid & 31, chunk = tid >> 5;
        float acc = 0.f;
        int i0 = chunk * 80;
        #pragma unroll 8
        for (int i = i0; i < i0 + 80; i++) acc += s_cat[i] * Wpool[i * E + e];
        s_cpart[chunk][e] = acc;
    }
    __syncthreads();

    if (tid < A) {
        float acc = 0.f;
        #pragma unroll
        for (int e = 0; e < E; e++) acc += s_pool[e] * Wv[e * A + tid];
        s_vsum[tid] = acc;
    }
    __syncthreads();

    if (tid < E) {
        float inter = bo[tid];
        #pragma unroll 8
        for (int a = 0; a < A; a++) inter += s_vsum[a] * Wo[a * E + tid];
        float cp = bpool[tid];
        #pragma unroll
        for (int c = 0; c < 8; c++) cp += s_cpart[c][tid];
        float ne = bnum[tid];
        #pragma unroll
        for (int j = 0; j < NNUM; j++) ne += nums[b * NNUM + j] * Wnum[j * E + tid];

        float* f = g_fused + (size_t)b * 128;
        f[tid]      = s_tgt[tid];
        f[32 + tid] = inter;
        f[64 + tid] = cp;
        f[96 + tid] = ne;
    }
}

// ---------------------------------------------------------------------------
// K2: h0 = relu(fused @ Wmlp + bmlp)   [B,256]; 8 rows/block, 128 blocks.
//     Wmlp [128][256] staged via cp.async in 16-k tiles, double buffered.
// ---------------------------------------------------------------------------
__device__ __forceinline__ void mlp_issue(float* wb, const float* __restrict__ Wmlp,
                                          int s, int tid)
{
    #pragma unroll
    for (int i = 0; i < 4; i++) {
        int flat = i * 256 + tid;          // float4 id in [0,1024)
        int k = flat >> 6;
        int c4 = (flat & 63) << 2;
        cp16(wb + k * 256 + c4, Wmlp + (s * 16 + k) * 256 + c4);
    }
}

__global__ __launch_bounds__(256) void k_mlp1(const float* __restrict__ Wmlp,
                                              const float* __restrict__ bmlp)
{
    __shared__ float xs[8 * 128];          // 4KB
    __shared__ float wb[2][16 * 256];      // 32KB
    const int r0 = blockIdx.x * 8;
    const int c = threadIdx.x;

    for (int i = c; i < 8 * 128; i += 256) xs[i] = g_fused[(size_t)r0 * 128 + i];

    mlp_issue(wb[0], Wmlp, 0, c); cp_commit();

    float acc[8];
    const float bc = bmlp[c];
    #pragma unroll
    for (int r = 0; r < 8; r++) acc[r] = bc;

    for (int s = 0; s < 8; s++) {
        int buf = s & 1;
        if (s < 7) { mlp_issue(wb[buf ^ 1], Wmlp, s + 1, c); cp_commit(); cp_wait1(); }
        else cp_wait0();
        __syncthreads();
        const float* wp = wb[buf];
        #pragma unroll
        for (int k4 = 0; k4 < 4; k4++) {
            float4 x4[8];
            #pragma unroll
            for (int r = 0; r < 8; r++)
                x4[r] = *(const float4*)(xs + r * 128 + s * 16 + k4 * 4);
            #pragma unroll
            for (int j = 0; j < 4; j++) {
                float w = wp[(k4 * 4 + j) * 256 + c];
                #pragma unroll
                for (int r = 0; r < 8; r++) {
                    float xv = (j == 0) ? x4[r].x : (j == 1) ? x4[r].y
                             : (j == 2) ? x4[r].z : x4[r].w;
                    acc[r] = fmaf(xv, w, acc[r]);
                }
            }
        }
        __syncthreads();
    }
    #pragma unroll
    for (int r = 0; r < 8; r++)
        g_h0[(size_t)(r0 + r) * H + c] = fmaxf(acc[r], 0.f);
}

// ---------------------------------------------------------------------------
// K3: QNN block  Y = X + ((X@W1+b1)*(X@W2+b2))@Wp + bp
//     8 rows/block, 256 threads, 128 blocks.
//     W1/W2/Wp staged through a cp.async double-buffered smem ring (32-k tiles).
//     mode: 0 = g_h0 -> g_h1 ; 1 = g_h1 -> final out (fused Wout dot)
// ---------------------------------------------------------------------------
__device__ __forceinline__ void qnn_issue_w12(float* wb,
                                              const float* __restrict__ W1,
                                              const float* __restrict__ W2,
                                              int s, int buf, int tid)
{
    #pragma unroll
    for (int i = 0; i < 16; i++) {
        int flat = i * 256 + tid;          // float4 id in [0,4096)
        int m = flat >> 11;                // 0 -> W1, 1 -> W2
        int rem = flat & 2047;
        int k = rem >> 6;
        int c4 = (rem & 63) << 2;
        const float* src = (m ? W2 : W1) + (s * 32 + k) * 256 + c4;
        float* dst = wb + ((buf * 2 + m) * 32 + k) * 256 + c4;
        cp16(dst, src);
    }
}

__device__ __forceinline__ void qnn_issue_wp(float* wb, const float* __restrict__ Wp,
                                             int s, int buf, int tid)
{
    #pragma unroll
    for (int i = 0; i < 8; i++) {
        int flat = i * 256 + tid;          // float4 id in [0,2048)
        int k = flat >> 6;
        int c4 = (flat & 63) << 2;
        cp16(wb + (buf * 2) * 8192 + k * 256 + c4, Wp + (s * 32 + k) * 256 + c4);
    }
}

__global__ __launch_bounds__(256) void k_qnn(
    const float* __restrict__ W1, const float* __restrict__ b1,
    const float* __restrict__ W2, const float* __restrict__ b2,
    const float* __restrict__ Wp, const float* __restrict__ bp,
    const float* __restrict__ Wout, const float* __restrict__ bout,
    float* __restrict__ out, int mode)
{
    extern __shared__ float sm[];
    float* xs = sm;             // [8][256]
    float* qs = sm + 2048;      // [8][256]
    float* wb = sm + 4096;      // [2 buf][2 mat][32][256]

    const int r0 = blockIdx.x * 8;
    const int c = threadIdx.x;
    const float* X = (mode == 0) ? g_h0 : g_h1;

    for (int i = c; i < 2048; i += 256) xs[i] = X[(size_t)r0 * 256 + i];

    qnn_issue_w12(wb, W1, W2, 0, 0, c); cp_commit();

    float a1[8], a2[8];
    const float b1c = b1[c], b2c = b2[c];
    #pragma unroll
    for (int r = 0; r < 8; r++) { a1[r] = b1c; a2[r] = b2c; }

    // ---- phase 1: a1 = X@W1+b1, a2 = X@W2+b2 ----
    for (int s = 0; s < 8; s++) {
        int buf = s & 1;
        if (s < 7) qnn_issue_w12(wb, W1, W2, s + 1, buf ^ 1, c);
        else       qnn_issue_wp(wb, Wp, 0, buf ^ 1, c);   // prefetch Wp stage 0
        cp_commit(); cp_wait1();
        __syncthreads();

        const float* w1p = wb + (buf * 2) * 8192;
        const float* w2p = w1p + 8192;
        #pragma unroll
        for (int k4 = 0; k4 < 8; k4++) {
            float4 x4[8];
            #pragma unroll
            for (int r = 0; r < 8; r++)
                x4[r] = *(const float4*)(xs + r * 256 + s * 32 + k4 * 4);
            #pragma unroll
            for (int j = 0; j < 4; j++) {
                float w1 = w1p[(k4 * 4 + j) * 256 + c];
                float w2 = w2p[(k4 * 4 + j) * 256 + c];
                #pragma unroll
                for (int r = 0; r < 8; r++) {
                    float xv = (j == 0) ? x4[r].x : (j == 1) ? x4[r].y
                             : (j == 2) ? x4[r].z : x4[r].w;
                    a1[r] = fmaf(xv, w1, a1[r]);
                    a2[r] = fmaf(xv, w2, a2[r]);
                }
            }
        }
        __syncthreads();
    }

    // quad = a1 * a2 -> smem (needed across all threads for phase 2)
    #pragma unroll
    for (int r = 0; r < 8; r++) qs[r * 256 + c] = a1[r] * a2[r];
    __syncthreads();

    // ---- phase 2: Y = X + quad@Wp + bp ----
    float ay[8];
    const float bpc = bp[c];
    #pragma unroll
    for (int r = 0; r < 8; r++) ay[r] = bpc;

    for (int p = 0; p < 8; p++) {
        int buf = p & 1;
        if (p < 7) { qnn_issue_wp(wb, Wp, p + 1, buf ^ 1, c); cp_commit(); cp_wait1(); }
        else cp_wait0();
        __syncthreads();

        const float* wpp = wb + (buf * 2) * 8192;
        #pragma unroll
        for (int k4 = 0; k4 < 8; k4++) {
            float4 q4[8];
            #pragma unroll
            for (int r = 0; r < 8; r++)
                q4[r] = *(const float4*)(qs + r * 256 + p * 32 + k4 * 4);
            #pragma unroll
            for (int j = 0; j < 4; j++) {
                float w = wpp[(k4 * 4 + j) * 256 + c];
                #pragma unroll
                for (int r = 0; r < 8; r++) {
                    float qv = (j == 0) ? q4[r].x : (j == 1) ? q4[r].y
                             : (j == 2) ? q4[r].z : q4[r].w;
                    ay[r] = fmaf(qv, w, ay[r]);
                }
            }
        }
        __syncthreads();
    }
    #pragma unroll
    for (int r = 0; r < 8; r++) ay[r] += xs[r * 256 + c];

    if (mode == 0) {
        #pragma unroll
        for (int r = 0; r < 8; r++) g_h1[(size_t)(r0 + r) * H + c] = ay[r];
    } else {
        const float wo = Wout[c];
        __shared__ float red[8];
        for (int r = 0; r < 8; r++) {
            float pv = ay[r] * wo;
            #pragma unroll
            for (int o = 16; o; o >>= 1) pv += __shfl_xor_sync(~0u, pv, o);
            if ((c & 31) == 0) red[c >> 5] = pv;
            __syncthreads();
            if (c == 0) {
                float s = 0.f;
                #pragma unroll
                for (int w = 0; w < 8; w++) s += red[w];
                out[r0 + r] = s + bout[0];
            }
            __syncthreads();
        }
    }
}

// ---------------------------------------------------------------------------
extern "C" void kernel_launch(void* const* d_in, const int* in_sizes, int n_in,
                              void* d_out, int out_size)
{
    const int*   cats    = (const int*)  d_in[0];
    const float* nums    = (const float*)d_in[1];
    const int*   seqs    = (const int*)  d_in[2];
    const int*   tgt_ids = (const int*)  d_in[3];
    const float* cat_emb = (const float*)d_in[4];
    const float* seq_emb = (const float*)d_in[5];
    const float* Wnum    = (const float*)d_in[6];
    const float* bnum    = (const float*)d_in[7];
    const float* Wq      = (const float*)d_in[8];
    const float* Wk      = (const float*)d_in[9];
    const float* Wv      = (const float*)d_in[10];
    const float* Wo      = (const float*)d_in[11];
    const float* bo      = (const float*)d_in[12];
    const float* Wpool   = (const float*)d_in[13];
    const float* bpool   = (const float*)d_in[14];
    const float* Wmlp    = (const float*)d_in[15];
    const float* bmlp    = (const float*)d_in[16];
    const float* q1_W1   = (const float*)d_in[17];
    const float* q1_b1   = (const float*)d_in[18];
    const float* q1_W2   = (const float*)d_in[19];
    const float* q1_b2   = (const float*)d_in[20];
    const float* q1_Wp   = (const float*)d_in[21];
    const float* q1_bp   = (const float*)d_in[22];
    const float* q2_W1   = (const float*)d_in[23];
    const float* q2_b1   = (const float*)d_in[24];
    const float* q2_W2   = (const float*)d_in[25];
    const float* q2_b2   = (const float*)d_in[26];
    const float* q2_Wp   = (const float*)d_in[27];
    const float* q2_bp   = (const float*)d_in[28];
    const float* Wout    = (const float*)d_in[29];
    const float* bout    = (const float*)d_in[30];
    float* out = (float*)d_out;

    // dynamic smem for k_qnn: xs(8KB) + qs(8KB) + weight ring(128KB) = 144KB
    static bool attr_set = false;
    const int QNN_SMEM = (2048 + 2048 + 2 * 2 * 8192) * (int)sizeof(float);
    if (!attr_set) {
        cudaFuncSetAttribute(k_qnn, cudaFuncAttributeMaxDynamicSharedMemorySize, QNN_SMEM);
        attr_set = true;
    }

    k_attn<<<B, 256>>>(cats, nums, seqs, tgt_ids, cat_emb, seq_emb,
                       Wnum, bnum, Wq, Wk, Wv, Wo, bo, Wpool, bpool);
    k_mlp1<<<B / 8, 256>>>(Wmlp, bmlp);
    k_qnn<<<B / 8, 256, QNN_SMEM>>>(q1_W1, q1_b1, q1_W2, q1_b2, q1_Wp, q1_bp,
                                    Wout, bout, out, 0);
    k_qnn<<<B / 8, 256, QNN_SMEM>>>(q2_W1, q2_b1, q2_W2, q2_b2, q2_Wp, q2_bp,
                                    Wout, bout, out, 1);
}

// round 11
// speedup vs baseline: 1.7570x; 1.2926x over previous
#include <cuda_runtime.h>
#include <cuda_bf16.h>

#define B 1024
#define L 1024
#define NCAT 20
#define NNUM 10
#define E 32
#define A 128
#define H 256
#define TOPK 30

// scratch (no cudaMalloc allowed)
__device__ float g_fused[B * 4 * E];   // [B,128]
__device__ float g_h1[B * H];

// ---------------------------------------------------------------------------
// cp.async helpers
// ---------------------------------------------------------------------------
__device__ __forceinline__ void cp16(void* dst, const void* src) {
    unsigned d = (unsigned)__cvta_generic_to_shared(dst);
    asm volatile("cp.async.cg.shared.global [%0], [%1], 16;" :: "r"(d), "l"(src));
}
__device__ __forceinline__ void cp_commit() { asm volatile("cp.async.commit_group;"); }
__device__ __forceinline__ void cp_wait1()  { asm volatile("cp.async.wait_group 1;"); }
__device__ __forceinline__ void cp_wait0()  { asm volatile("cp.async.wait_group 0;"); }

// ---------------------------------------------------------------------------
// K1: one block per batch row. Attention (score -> top30 via radix select ->
//     softmax -> pool) + small projections -> fused[b, 0:128]
// ---------------------------------------------------------------------------
__device__ __forceinline__ unsigned f2key(float f) {
    unsigned u = __float_as_uint(f);
    return (u & 0x80000000u) ? ~u : (u | 0x80000000u);   // monotone order map
}

__global__ __launch_bounds__(256) void k_attn(
    const int* __restrict__ cats, const float* __restrict__ nums,
    const int* __restrict__ seqs, const int* __restrict__ tgt_ids,
    const float* __restrict__ cat_emb, const float* __restrict__ seq_emb,
    const float* __restrict__ Wnum, const float* __restrict__ bnum,
    const float* __restrict__ Wq, const float* __restrict__ Wk,
    const float* __restrict__ Wv, const float* __restrict__ Wo,
    const float* __restrict__ bo, const float* __restrict__ Wpool,
    const float* __restrict__ bpool)
{
    const int b = blockIdx.x;
    const int tid = threadIdx.x;
    const int lane = tid & 31;
    const int warp = tid >> 5;

    __shared__ float    s_scores[L];
    __shared__ unsigned s_key[L];
    __shared__ int      s_hist[256];
    __shared__ unsigned s_prefix;
    __shared__ int      s_need;
    __shared__ int      s_wcnt[8];
    __shared__ int      s_gbase;
    __shared__ int      s_tiec;
    __shared__ float s_tgt[E];
    __shared__ float s_q[A];
    __shared__ float s_qk[E];
    __shared__ float s_cat[NCAT * E];
    __shared__ float s_cpart[8][E];
    __shared__ float s_topv[TOPK];
    __shared__ int   s_topi[TOPK];
    __shared__ float s_w[TOPK];
    __shared__ float s_pool[E];
    __shared__ float s_vsum[A];

    const int tgt = tgt_ids[b];
    if (tid < E) s_tgt[tid] = cat_emb[(size_t)tgt * E + tid];
    for (int i = tid; i < NCAT * E; i += 256) {
        int j = i >> 5, e = i & 31;
        s_cat[i] = cat_emb[(size_t)cats[b * NCAT + j] * E + e];
    }
    __syncthreads();

    // q = tgt_e @ Wq  [A]
    if (tid < A) {
        float acc = 0.f;
        #pragma unroll
        for (int e = 0; e < E; e++) acc += s_tgt[e] * Wq[e * A + tid];
        s_q[tid] = acc;
    }
    __syncthreads();

    // qk[e] = (Wk @ q)[e] / sqrt(A)
    {
        #pragma unroll
        for (int i = 0; i < 4; i++) {
            int e = warp * 4 + i;
            float acc = Wk[e * A + lane]      * s_q[lane]
                      + Wk[e * A + lane + 32] * s_q[lane + 32]
                      + Wk[e * A + lane + 64] * s_q[lane + 64]
                      + Wk[e * A + lane + 96] * s_q[lane + 96];
            #pragma unroll
            for (int o = 16; o; o >>= 1) acc += __shfl_xor_sync(~0u, acc, o);
            if (lane == 0) s_qk[e] = acc * 0.08838834764831845f;
        }
    }
    __syncthreads();

    // scores[l] = seq_emb[seqs[b,l]] . qk ;  key for radix select
    for (int l = tid; l < L; l += 256) {
        const float4* row = (const float4*)(seq_emb + (size_t)seqs[b * L + l] * E);
        float acc = 0.f;
        #pragma unroll
        for (int c = 0; c < 8; c++) {
            float4 r = row[c];
            acc += r.x * s_qk[4 * c] + r.y * s_qk[4 * c + 1]
                 + r.z * s_qk[4 * c + 2] + r.w * s_qk[4 * c + 3];
        }
        s_scores[l] = acc;
        s_key[l] = f2key(acc);
    }
    if (tid == 0) { s_prefix = 0u; s_need = TOPK; s_gbase = 0; s_tiec = 0; }
    __syncthreads();

    // ---- radix select: find 30th-largest key t (MSB-first byte passes) ----
    for (int p = 3; p >= 0; p--) {
        s_hist[tid] = 0;
        __syncthreads();
        const unsigned pref = s_prefix;
        const int need = s_need;
        const int sh_hi = 8 * p + 8;
        #pragma unroll
        for (int ch = 0; ch < 4; ch++) {
            unsigned k = s_key[ch * 256 + tid];
            bool match = (p == 3) || (((k ^ pref) >> sh_hi) == 0u);
            if (match) atomicAdd(&s_hist[(k >> (8 * p)) & 255], 1);
        }
        __syncthreads();
        if (warp == 0) {
            int b0 = 255 - 8 * lane;
            int loc[8], sum = 0;
            #pragma unroll
            for (int j = 0; j < 8; j++) { loc[j] = s_hist[b0 - j]; sum += loc[j]; }
            int inc = sum;
            #pragma unroll
            for (int o = 1; o < 32; o <<= 1) {
                int t = __shfl_up_sync(~0u, inc, o);
                if (lane >= o) inc += t;
            }
            int above = inc - sum;
            bool isx = (above < need) && (above + sum >= need);
            unsigned mb = __ballot_sync(~0u, isx);
            int xl = __ffs(mb) - 1;
            if (lane == xl) {
                int acc = above, bin = b0;
                #pragma unroll
                for (int j = 0; j < 8; j++) {
                    if (acc + loc[j] >= need) { bin = b0 - j; break; }
                    acc += loc[j];
                }
                s_prefix = pref | ((unsigned)bin << (8 * p));
                s_need = need - acc;
            }
        }
        __syncthreads();
    }
    const unsigned tkey = s_prefix;
    const int m = s_need;              // slots to fill with key == tkey
    const int cnt_gt = TOPK - m;

    // ---- deterministic compaction of keys > tkey (ballot + scan) ----
    #pragma unroll
    for (int ch = 0; ch < 4; ch++) {
        int l = ch * 256 + tid;
        bool sel = s_key[l] > tkey;
        unsigned mb = __ballot_sync(~0u, sel);
        int rank = __popc(mb & ((1u << lane) - 1));
        if (lane == 0) s_wcnt[warp] = __popc(mb);
        __syncthreads();
        if (tid == 0) {
            int off = s_gbase;
            #pragma unroll
            for (int w = 0; w < 8; w++) { int c = s_wcnt[w]; s_wcnt[w] = off; off += c; }
            s_gbase = off;
        }
        __syncthreads();
        if (sel) {
            int slot = s_wcnt[warp] + rank;
            s_topv[slot] = s_scores[l];
            s_topi[slot] = l;
        }
        __syncthreads();
    }
    // ties (almost always exactly 1 element)
    #pragma unroll
    for (int ch = 0; ch < 4; ch++) {
        int l = ch * 256 + tid;
        if (s_key[l] == tkey) {
            int j = atomicAdd(&s_tiec, 1);
            if (j < m) { s_topv[cnt_gt + j] = s_scores[l]; s_topi[cnt_gt + j] = l; }
        }
    }
    __syncthreads();

    // softmax over the 30 values (order-invariant)
    if (tid < 32) {
        float v = (tid < TOPK) ? s_topv[tid] : -1e30f;
        float mx = v;
        #pragma unroll
        for (int o = 16; o; o >>= 1) mx = fmaxf(mx, __shfl_xor_sync(~0u, mx, o));
        float ex = (tid < TOPK) ? __expf(v - mx) : 0.f;
        float s = ex;
        #pragma unroll
        for (int o = 16; o; o >>= 1) s += __shfl_xor_sync(~0u, s, o);
        if (tid < TOPK) s_w[tid] = ex / s;
    }
    __syncthreads();

    if (tid < E) {
        float acc = 0.f;
        #pragma unroll 5
        for (int k = 0; k < TOPK; k++)
            acc += s_w[k] * seq_emb[(size_t)seqs[b * L + s_topi[k]] * E + tid];
        s_pool[tid] = acc;
    }
    {
        int e = tid & 31, chunk = tid >> 5;
        float acc = 0.f;
        int i0 = chunk * 80;
        #pragma unroll 8
        for (int i = i0; i < i0 + 80; i++) acc += s_cat[i] * Wpool[i * E + e];
        s_cpart[chunk][e] = acc;
    }
    __syncthreads();

    if (tid < A) {
        float acc = 0.f;
        #pragma unroll
        for (int e = 0; e < E; e++) acc += s_pool[e] * Wv[e * A + tid];
        s_vsum[tid] = acc;
    }
    __syncthreads();

    if (tid < E) {
        float inter = bo[tid];
        #pragma unroll 8
        for (int a = 0; a < A; a++) inter += s_vsum[a] * Wo[a * E + tid];
        float cp = bpool[tid];
        #pragma unroll
        for (int c = 0; c < 8; c++) cp += s_cpart[c][tid];
        float ne = bnum[tid];
        #pragma unroll
        for (int j = 0; j < NNUM; j++) ne += nums[b * NNUM + j] * Wnum[j * E + tid];

        float* f = g_fused + (size_t)b * 128;
        f[tid]      = s_tgt[tid];
        f[32 + tid] = inter;
        f[64 + tid] = cp;
        f[96 + tid] = ne;
    }
}

// ---------------------------------------------------------------------------
// K3: QNN block, 512 threads (halves own 4 rows each), 128 blocks.
//     mode 0 additionally computes h0 = relu(fused@Wmlp+bmlp) as a pipelined
//     prologue (k_mlp1 fused away). mode 1 fuses the final Wout dot.
//     Y = X + ((X@W1+b1)*(X@W2+b2))@Wp + bp
// ---------------------------------------------------------------------------
__device__ __forceinline__ void qnn_issue_w12(float* wb,
                                              const float* __restrict__ W1,
                                              const float* __restrict__ W2,
                                              int s, int buf, int tid)
{
    #pragma unroll
    for (int i = 0; i < 8; i++) {
        int flat = i * 512 + tid;          // float4 id in [0,4096)
        int mtx = flat >> 11;              // 0 -> W1, 1 -> W2
        int rem = flat & 2047;
        int k = rem >> 6;
        int c4 = (rem & 63) << 2;
        const float* src = (mtx ? W2 : W1) + (s * 32 + k) * 256 + c4;
        float* dst = wb + ((buf * 2 + mtx) * 32 + k) * 256 + c4;
        cp16(dst, src);
    }
}

__device__ __forceinline__ void qnn_issue_one(float* wb, const float* __restrict__ W,
                                              int s, int buf, int tid)
{
    #pragma unroll
    for (int i = 0; i < 4; i++) {
        int flat = i * 512 + tid;          // float4 id in [0,2048)
        int k = flat >> 6;
        int c4 = (flat & 63) << 2;
        cp16(wb + (buf * 2) * 8192 + k * 256 + c4, W + (s * 32 + k) * 256 + c4);
    }
}

__global__ __launch_bounds__(512) void k_qnn(
    const float* __restrict__ Wmlp, const float* __restrict__ bmlp,
    const float* __restrict__ W1, const float* __restrict__ b1,
    const float* __restrict__ W2, const float* __restrict__ b2,
    const float* __restrict__ Wp, const float* __restrict__ bp,
    const float* __restrict__ Wout, const float* __restrict__ bout,
    float* __restrict__ out, int mode)
{
    extern __shared__ float sm[];
    float* xs = sm;             // [8][256]
    float* qs = sm + 2048;      // [8][256] (also stages fused[8][128] in mode 0)
    float* wb = sm + 4096;      // ring: [2 buf][2 mat][32][256]

    const int tid = threadIdx.x;
    const int c = tid & 255;
    const int half = tid >> 8;
    const int rb = half * 4;               // first of this thread's 4 rows
    const int r0 = blockIdx.x * 8;

    if (mode == 0) {
        // -------- fused MLP prologue: xs = relu(fused @ Wmlp + bmlp) --------
        float* fs = qs;                     // [8][128]
        for (int i = tid; i < 8 * 128; i += 512) fs[i] = g_fused[(size_t)r0 * 128 + i];
        qnn_issue_one(wb, Wmlp, 0, 0, tid); cp_commit();

        float acc[4];
        const float bmc = bmlp[c];
        #pragma unroll
        for (int r = 0; r < 4; r++) acc[r] = bmc;

        for (int s = 0; s < 4; s++) {
            int buf = s & 1;
            if (s < 3) qnn_issue_one(wb, Wmlp, s + 1, buf ^ 1, tid);
            else       qnn_issue_w12(wb, W1, W2, 0, buf ^ 1, tid);  // prefetch phase1
            cp_commit(); cp_wait1();
            __syncthreads();
            const float* wt = wb + (buf * 2) * 8192;
            #pragma unroll
            for (int k4 = 0; k4 < 8; k4++) {
                float4 f4[4];
                #pragma unroll
                for (int r = 0; r < 4; r++)
                    f4[r] = *(const float4*)(fs + (rb + r) * 128 + s * 32 + k4 * 4);
                #pragma unroll
                for (int j = 0; j < 4; j++) {
                    float w = wt[(k4 * 4 + j) * 256 + c];
                    #pragma unroll
                    for (int r = 0; r < 4; r++) {
                        float xv = (j == 0) ? f4[r].x : (j == 1) ? f4[r].y
                                 : (j == 2) ? f4[r].z : f4[r].w;
                        acc[r] = fmaf(xv, w, acc[r]);
                    }
                }
            }
            __syncthreads();
        }
        #pragma unroll
        for (int r = 0; r < 4; r++) xs[(rb + r) * 256 + c] = fmaxf(acc[r], 0.f);
        __syncthreads();
    } else {
        for (int i = tid; i < 2048; i += 512) xs[i] = g_h1[(size_t)r0 * 256 + i];
        qnn_issue_w12(wb, W1, W2, 0, 0, tid); cp_commit();
    }

    float a1[4], a2[4];
    const float b1c = b1[c], b2c = b2[c];
    #pragma unroll
    for (int r = 0; r < 4; r++) { a1[r] = b1c; a2[r] = b2c; }

    // ---- phase 1: a1 = X@W1+b1, a2 = X@W2+b2 (4 rows per thread) ----
    for (int s = 0; s < 8; s++) {
        int buf = s & 1;
        if (s < 7) qnn_issue_w12(wb, W1, W2, s + 1, buf ^ 1, tid);
        else       qnn_issue_one(wb, Wp, 0, buf ^ 1, tid);   // prefetch Wp stage 0
        cp_commit(); cp_wait1();
        __syncthreads();

        const float* w1p = wb + (buf * 2) * 8192;
        const float* w2p = w1p + 8192;
        #pragma unroll
        for (int k4 = 0; k4 < 8; k4++) {
            float4 x4[4];
            #pragma unroll
            for (int r = 0; r < 4; r++)
                x4[r] = *(const float4*)(xs + (rb + r) * 256 + s * 32 + k4 * 4);
            #pragma unroll
            for (int j = 0; j < 4; j++) {
                float w1 = w1p[(k4 * 4 + j) * 256 + c];
                float w2 = w2p[(k4 * 4 + j) * 256 + c];
                #pragma unroll
                for (int r = 0; r < 4; r++) {
                    float xv = (j == 0) ? x4[r].x : (j == 1) ? x4[r].y
                             : (j == 2) ? x4[r].z : x4[r].w;
                    a1[r] = fmaf(xv, w1, a1[r]);
                    a2[r] = fmaf(xv, w2, a2[r]);
                }
            }
        }
        __syncthreads();
    }

    // quad -> smem (full 8x256 needed by both halves' phase 2 reads of own rows)
    #pragma unroll
    for (int r = 0; r < 4; r++) qs[(rb + r) * 256 + c] = a1[r] * a2[r];
    __syncthreads();

    // ---- phase 2: Y = X + quad@Wp + bp ----
    float ay[4];
    const float bpc = bp[c];
    #pragma unroll
    for (int r = 0; r < 4; r++) ay[r] = bpc;

    for (int p = 0; p < 8; p++) {
        int buf = p & 1;
        if (p < 7) { qnn_issue_one(wb, Wp, p + 1, buf ^ 1, tid); cp_commit(); cp_wait1(); }
        else cp_wait0();
        __syncthreads();

        const float* wpp = wb + (buf * 2) * 8192;
        #pragma unroll
        for (int k4 = 0; k4 < 8; k4++) {
            float4 q4[4];
            #pragma unroll
            for (int r = 0; r < 4; r++)
                q4[r] = *(const float4*)(qs + (rb + r) * 256 + p * 32 + k4 * 4);
            #pragma unroll
            for (int j = 0; j < 4; j++) {
                float w = wpp[(k4 * 4 + j) * 256 + c];
                #pragma unroll
                for (int r = 0; r < 4; r++) {
                    float qv = (j == 0) ? q4[r].x : (j == 1) ? q4[r].y
                             : (j == 2) ? q4[r].z : q4[r].w;
                    ay[r] = fmaf(qv, w, ay[r]);
                }
            }
        }
        __syncthreads();
    }
    #pragma unroll
    for (int r = 0; r < 4; r++) ay[r] += xs[(rb + r) * 256 + c];

    if (mode == 0) {
        #pragma unroll
        for (int r = 0; r < 4; r++)
            g_h1[(size_t)(r0 + rb + r) * H + c] = ay[r];
    } else {
        // final: out[row] = ay_row . Wout + bout (deterministic fixed-order sum)
        __shared__ float red[16][4];
        const float wo = Wout[c];
        const int warp = tid >> 5, lane = tid & 31;
        float pv[4];
        #pragma unroll
        for (int r = 0; r < 4; r++) {
            pv[r] = ay[r] * wo;
            #pragma unroll
            for (int o = 16; o; o >>= 1) pv[r] += __shfl_xor_sync(~0u, pv[r], o);
        }
        if (lane == 0) {
            #pragma unroll
            for (int r = 0; r < 4; r++) red[warp][r] = pv[r];
        }
        __syncthreads();
        if (tid < 8) {
            int h = tid >> 2, rl = tid & 3;
            float s = bout[0];
            #pragma unroll
            for (int w = 0; w < 8; w++) s += red[h * 8 + w][rl];
            out[r0 + tid] = s;
        }
    }
}

// ---------------------------------------------------------------------------
extern "C" void kernel_launch(void* const* d_in, const int* in_sizes, int n_in,
                              void* d_out, int out_size)
{
    const int*   cats    = (const int*)  d_in[0];
    const float* nums    = (const float*)d_in[1];
    const int*   seqs    = (const int*)  d_in[2];
    const int*   tgt_ids = (const int*)  d_in[3];
    const float* cat_emb = (const float*)d_in[4];
    const float* seq_emb = (const float*)d_in[5];
    const float* Wnum    = (const float*)d_in[6];
    const float* bnum    = (const float*)d_in[7];
    const float* Wq      = (const float*)d_in[8];
    const float* Wk      = (const float*)d_in[9];
    const float* Wv      = (const float*)d_in[10];
    const float* Wo      = (const float*)d_in[11];
    const float* bo      = (const float*)d_in[12];
    const float* Wpool   = (const float*)d_in[13];
    const float* bpool   = (const float*)d_in[14];
    const float* Wmlp    = (const float*)d_in[15];
    const float* bmlp    = (const float*)d_in[16];
    const float* q1_W1   = (const float*)d_in[17];
    const float* q1_b1   = (const float*)d_in[18];
    const float* q1_W2   = (const float*)d_in[19];
    const float* q1_b2   = (const float*)d_in[20];
    const float* q1_Wp   = (const float*)d_in[21];
    const float* q1_bp   = (const float*)d_in[22];
    const float* q2_W1   = (const float*)d_in[23];
    const float* q2_b1   = (const float*)d_in[24];
    const float* q2_W2   = (const float*)d_in[25];
    const float* q2_b2   = (const float*)d_in[26];
    const float* q2_Wp   = (const float*)d_in[27];
    const float* q2_bp   = (const float*)d_in[28];
    const float* Wout    = (const float*)d_in[29];
    const float* bout    = (const float*)d_in[30];
    float* out = (float*)d_out;

    // dynamic smem for k_qnn: xs(8KB) + qs(8KB) + weight ring(128KB) = 144KB
    static bool attr_set = false;
    const int QNN_SMEM = (2048 + 2048 + 2 * 2 * 8192) * (int)sizeof(float);
    if (!attr_set) {
        cudaFuncSetAttribute(k_qnn, cudaFuncAttributeMaxDynamicSharedMemorySize, QNN_SMEM);
        attr_set = true;
    }

    k_attn<<<B, 256>>>(cats, nums, seqs, tgt_ids, cat_emb, seq_emb,
                       Wnum, bnum, Wq, Wk, Wv, Wo, bo, Wpool, bpool);
    k_qnn<<<B / 8, 512, QNN_SMEM>>>(Wmlp, bmlp,
                                    q1_W1, q1_b1, q1_W2, q1_b2, q1_Wp, q1_bp,
                                    Wout, bout, out, 0);
    k_qnn<<<B / 8, 512, QNN_SMEM>>>(Wmlp, bmlp,
                                    q2_W1, q2_b1, q2_W2, q2_b2, q2_Wp, q2_bp,
                                    Wout, bout, out, 1);
}